// round 12
// baseline (speedup 1.0000x reference)
#include <cuda_runtime.h>

// out[n, k=9*i+j, h, w] = sum_z A[n,z,h,w] * B[n,z, h+j-4, w+i-4]  (zero pad)
// N=8, Z=128, H=W=160.
//
// CTA tile TW=32 x TH=8. Threads (tx=4, h=8, j=9) = 288; warp == one j.
// Thread: 8 consecutive pixels, one row, 9 i-shifts -> 72 scalar accumulators.
// ZC=8 z-chunks (16 total), TRIPLE-buffered dynamic smem (93 KB) via
// cp.async.cg (zfill halo), single __syncthreads per chunk.

#define N_  8
#define Z_  128
#define H_  160
#define W_  160
#define TW  32
#define TH  8
#define ZC  8
#define NCH (Z_ / ZC)     // 16
#define AROW 36
#define BROW 44
#define BRN  16           // TH + 8
#define NT  288

#define ASZ (ZC * TH * AROW)      // 2304 floats per A buffer
#define BSZ (ZC * BRN * BROW)     // 5632 floats per B buffer
#define ABUF_TOTAL (3 * ASZ)      // 6912
#define SMEM_FLOATS (3 * ASZ + 3 * BSZ)   // 23808 floats = 95232 B

__global__ __launch_bounds__(NT, 2)
void corr_kernel(const float* __restrict__ A,
                 const float* __restrict__ B,
                 float* __restrict__ out)
{
    extern __shared__ float SM[];   // [3*ASZ A buffers][3*BSZ B buffers]

    const int tid = threadIdx.x;
    const int tx = tid & 3;          // w = w0 + 8*tx .. +7
    const int h  = (tid >> 2) & 7;
    const int j  = tid >> 5;         // warp index

    const int w0 = blockIdx.x * TW;
    const int h0 = blockIdx.y * TH;
    const int n  = blockIdx.z;

    const size_t plane = (size_t)H_ * W_;
    const float* Abase = A + (size_t)n * Z_ * plane;
    const float* Bbase = B + (size_t)n * Z_ * plane;

    // ------- fixed fill roles (computed once) -------
    // B: ZC*16*10 = 1280 float4/chunk, 5 slots (idx = tid + 288*s)
    unsigned boff[5], bsm[5];
    int bszv[5]; bool bact[5];
    #pragma unroll
    for (int s = 0; s < 5; s++) {
        int idx = tid + s * NT;
        bool act = idx < ZC * BRN * 10;
        int ii = act ? idx : 0;
        int z = ii / 160;
        int rem = ii - z * 160;
        int r = rem / 10;
        int c = rem - r * 10;
        int gh = h0 - 4 + r;
        int gw = w0 - 4 + 4 * c;
        bool v = ((unsigned)gh < H_) && ((unsigned)gw <= (W_ - 4));
        bact[s] = act;
        bszv[s] = v ? 16 : 0;
        boff[s] = v ? (unsigned)(z * plane + gh * W_ + gw) : 0u;
        bsm[s] = (unsigned)__cvta_generic_to_shared(
                     &SM[ABUF_TOTAL + z * (BRN * BROW) + r * BROW + 4 * c]);
    }
    // A: ZC*8*8 = 512 float4/chunk, 2 slots
    unsigned aoff[2], asmv[2]; bool aact[2];
    #pragma unroll
    for (int s = 0; s < 2; s++) {
        int idx = tid + s * NT;
        bool act = idx < ZC * TH * 8;
        int ii = act ? idx : 0;
        int z = ii >> 6;
        int r = (ii >> 3) & 7;
        int c = ii & 7;
        aact[s] = act;
        aoff[s] = (unsigned)(z * plane + (h0 + r) * W_ + w0 + 4 * c);
        asmv[s] = (unsigned)__cvta_generic_to_shared(
                      &SM[z * (TH * AROW) + r * AROW + 4 * c]);
    }

    // read-side base pointers (buffer 0)
    const float* aRd0 = &SM[h * AROW + 8 * tx];
    const float* bRd0 = &SM[ABUF_TOTAL + (h + j) * BROW + 8 * tx];

    float acc[9][8];
    #pragma unroll
    for (int i = 0; i < 9; i++)
        #pragma unroll
        for (int p = 0; p < 8; p++)
            acc[i][p] = 0.0f;

    auto issue = [&](int chunk, int buf) {
        const float* bsrc = Bbase + (size_t)chunk * ZC * plane;
        const float* asrc = Abase + (size_t)chunk * ZC * plane;
        const unsigned bo = (unsigned)(buf * (BSZ * 4));
        const unsigned ao = (unsigned)(buf * (ASZ * 4));
        #pragma unroll
        for (int s = 0; s < 5; s++) {
            if (bact[s])
                asm volatile("cp.async.cg.shared.global [%0], [%1], 16, %2;"
                             :: "r"(bsm[s] + bo), "l"(bsrc + boff[s]), "r"(bszv[s]));
        }
        #pragma unroll
        for (int s = 0; s < 2; s++) {
            if (aact[s])
                asm volatile("cp.async.cg.shared.global [%0], [%1], 16, 16;"
                             :: "r"(asmv[s] + ao), "l"(asrc + aoff[s]));
        }
        asm volatile("cp.async.commit_group;");
    };

    // prologue: 2 chunks in flight
    issue(0, 0);
    issue(1, 1);

    int bufc = 0;   // buffer holding chunk ch
    for (int ch = 0; ch < NCH; ch++) {
        if (ch < NCH - 1) asm volatile("cp.async.wait_group 1;");
        else              asm volatile("cp.async.wait_group 0;");
        __syncthreads();   // chunk ch visible; buffer (ch+2)%3 fully drained

        int nb = bufc + 2; if (nb >= 3) nb -= 3;
        if (ch + 2 < NCH) issue(ch + 2, nb);

        const float* aRd = aRd0 + bufc * ASZ;
        const float* bRd = bRd0 + bufc * BSZ;

        #pragma unroll
        for (int z = 0; z < ZC; z++) {
            const float4 a0 = *(const float4*)(aRd + z * (TH * AROW));
            const float4 a1 = *(const float4*)(aRd + z * (TH * AROW) + 4);
            const float4 b0 = *(const float4*)(bRd + z * (BRN * BROW));
            const float4 b1 = *(const float4*)(bRd + z * (BRN * BROW) + 4);
            const float4 b2 = *(const float4*)(bRd + z * (BRN * BROW) + 8);
            const float4 b3 = *(const float4*)(bRd + z * (BRN * BROW) + 12);

            const float a[8] = {a0.x, a0.y, a0.z, a0.w, a1.x, a1.y, a1.z, a1.w};
            const float b[16] = {b0.x, b0.y, b0.z, b0.w, b1.x, b1.y, b1.z, b1.w,
                                 b2.x, b2.y, b2.z, b2.w, b3.x, b3.y, b3.z, b3.w};

            #pragma unroll
            for (int i = 0; i < 9; i++)
                #pragma unroll
                for (int p = 0; p < 8; p++)
                    acc[i][p] += a[p] * b[p + i];
        }

        bufc = (bufc == 2) ? 0 : bufc + 1;
    }

    // ------- store: 18 x STG.128 -------
    float* ob = out + (((size_t)n * 81 + j) * H_ + (h0 + h)) * W_ + w0 + 8 * tx;
    #pragma unroll
    for (int i = 0; i < 9; i++) {
        *(float4*)(ob + (size_t)(9 * i) * plane) =
            make_float4(acc[i][0], acc[i][1], acc[i][2], acc[i][3]);
        *(float4*)(ob + (size_t)(9 * i) * plane + 4) =
            make_float4(acc[i][4], acc[i][5], acc[i][6], acc[i][7]);
    }
}

extern "C" void kernel_launch(void* const* d_in, const int* in_sizes, int n_in,
                              void* d_out, int out_size)
{
    const float* imgA = (const float*)d_in[0];
    const float* imgB = (const float*)d_in[1];
    float* out = (float*)d_out;

    const int smem_bytes = SMEM_FLOATS * 4;   // 95232 B
    cudaFuncSetAttribute(corr_kernel,
                         cudaFuncAttributeMaxDynamicSharedMemorySize, smem_bytes);

    dim3 grid(W_ / TW, H_ / TH, N_);
    corr_kernel<<<grid, NT, smem_bytes>>>(imgA, imgB, out);
}

// round 13
// speedup vs baseline: 1.0377x; 1.0377x over previous
#include <cuda_runtime.h>

// out[n, k=9*i+j, h, w] = sum_z A[n,z,h,w] * B[n,z, h+j-4, w+i-4]  (zero pad)
// N=8, Z=128, H=W=160.
//
// CTA tile TW=32 x TH=8. Threads (tx=4, h=8, j=9) = 288; warp == one j.
// Thread: 8 consecutive pixels, one row, 9 i-shifts -> 72 scalar accumulators.
// ZC=4 z-chunks, triple-buffered smem via cp.async.cg (zfill halo), one
// barrier per chunk. z-loop operands are SOFTWARE-PIPELINED: z+1's six
// LDS.128 are staged in registers while z's 72 FFMA execute.

#define N_  8
#define Z_  128
#define H_  160
#define W_  160
#define TW  32
#define TH  8
#define ZC  4
#define NCH (Z_ / ZC)     // 32
#define AROW 36
#define BROW 44
#define BRN  16           // TH + 8
#define NT  288

#define ASZ (ZC * TH * AROW)      // floats per A buffer
#define BSZ (ZC * BRN * BROW)     // floats per B buffer

__global__ __launch_bounds__(NT, 2)
void corr_kernel(const float* __restrict__ A,
                 const float* __restrict__ B,
                 float* __restrict__ out)
{
    __shared__ float As[3][ZC][TH][AROW];   // 3 * 4.5 KB
    __shared__ float Bs[3][ZC][BRN][BROW];  // 3 * 11 KB  (46.5 KB)

    const int tid = threadIdx.x;
    const int tx = tid & 3;          // w = w0 + 8*tx .. +7
    const int h  = (tid >> 2) & 7;
    const int j  = tid >> 5;         // warp index

    const int w0 = blockIdx.x * TW;
    const int h0 = blockIdx.y * TH;
    const int n  = blockIdx.z;

    const size_t plane = (size_t)H_ * W_;
    const float* Abase = A + (size_t)n * Z_ * plane;
    const float* Bbase = B + (size_t)n * Z_ * plane;

    // ------- fixed fill roles (computed once) -------
    // B: ZC*16*10 = 640 float4/chunk, slots idx = tid + 288*s, s=0..2
    unsigned boff[3], bsm[3];
    int bszv[3]; bool bact[3];
    #pragma unroll
    for (int s = 0; s < 3; s++) {
        int idx = tid + s * NT;
        bool act = idx < ZC * BRN * 10;
        int ii = act ? idx : 0;
        int z = ii / 160;
        int rem = ii - z * 160;
        int r = rem / 10;
        int c = rem - r * 10;
        int gh = h0 - 4 + r;
        int gw = w0 - 4 + 4 * c;
        bool v = ((unsigned)gh < H_) && ((unsigned)gw <= (W_ - 4));
        bact[s] = act;
        bszv[s] = v ? 16 : 0;
        boff[s] = v ? (unsigned)(z * plane + gh * W_ + gw) : 0u;
        bsm[s] = (unsigned)__cvta_generic_to_shared(&Bs[0][z][r][4 * c]);
    }
    // A: ZC*8*8 = 256 float4/chunk (tid < 256)
    const bool aact = tid < ZC * TH * 8;
    int ai = aact ? tid : 0;
    int az = ai >> 6;
    int ar = (ai >> 3) & 7;
    int ac = ai & 7;
    const unsigned aoff = (unsigned)(az * plane + (h0 + ar) * W_ + w0 + 4 * ac);
    const unsigned asm0 = (unsigned)__cvta_generic_to_shared(&As[0][az][ar][4 * ac]);

    // read-side base pointers (buffer 0)
    const float* aRd0 = &As[0][0][h][8 * tx];
    const float* bRd0 = &Bs[0][0][h + j][8 * tx];

    float acc[9][8];
    #pragma unroll
    for (int i = 0; i < 9; i++)
        #pragma unroll
        for (int p = 0; p < 8; p++)
            acc[i][p] = 0.0f;

    auto issue = [&](int chunk, int buf) {
        const float* bsrc = Bbase + (size_t)chunk * ZC * plane;
        const float* asrc = Abase + (size_t)chunk * ZC * plane;
        const unsigned bo = (unsigned)(buf * (BSZ * 4));
        const unsigned ao = (unsigned)(buf * (ASZ * 4));
        #pragma unroll
        for (int s = 0; s < 3; s++) {
            if (bact[s])
                asm volatile("cp.async.cg.shared.global [%0], [%1], 16, %2;"
                             :: "r"(bsm[s] + bo), "l"(bsrc + boff[s]), "r"(bszv[s]));
        }
        if (aact)
            asm volatile("cp.async.cg.shared.global [%0], [%1], 16, 16;"
                         :: "r"(asm0 + ao), "l"(asrc + aoff));
        asm volatile("cp.async.commit_group;");
    };

    // prologue: 2 chunks in flight
    issue(0, 0);
    issue(1, 1);

    int bufc = 0;   // buffer holding chunk ch
    for (int ch = 0; ch < NCH; ch++) {
        if (ch < NCH - 1) asm volatile("cp.async.wait_group 1;");
        else              asm volatile("cp.async.wait_group 0;");
        __syncthreads();   // chunk ch visible; buffer (ch+2)%3 fully drained

        int nb = bufc + 2; if (nb >= 3) nb -= 3;
        if (ch + 2 < NCH) issue(ch + 2, nb);

        const float* aRd = aRd0 + bufc * ASZ;
        const float* bRd = bRd0 + bufc * BSZ;

        // ---- software-pipelined z-loop ----
        float4 A0 = *(const float4*)(aRd);
        float4 A1 = *(const float4*)(aRd + 4);
        float4 B0 = *(const float4*)(bRd);
        float4 B1 = *(const float4*)(bRd + 4);
        float4 B2 = *(const float4*)(bRd + 8);
        float4 B3 = *(const float4*)(bRd + 12);

        #pragma unroll
        for (int z = 0; z < ZC; z++) {
            const float4 a0 = A0, a1 = A1;
            const float4 b0 = B0, b1 = B1, b2 = B2, b3 = B3;

            if (z + 1 < ZC) {   // stage z+1 while z computes
                const float* ap = aRd + (z + 1) * (TH * AROW);
                const float* bp = bRd + (z + 1) * (BRN * BROW);
                A0 = *(const float4*)(ap);
                A1 = *(const float4*)(ap + 4);
                B0 = *(const float4*)(bp);
                B1 = *(const float4*)(bp + 4);
                B2 = *(const float4*)(bp + 8);
                B3 = *(const float4*)(bp + 12);
            }

            const float a[8] = {a0.x, a0.y, a0.z, a0.w, a1.x, a1.y, a1.z, a1.w};
            const float b[16] = {b0.x, b0.y, b0.z, b0.w, b1.x, b1.y, b1.z, b1.w,
                                 b2.x, b2.y, b2.z, b2.w, b3.x, b3.y, b3.z, b3.w};

            #pragma unroll
            for (int i = 0; i < 9; i++)
                #pragma unroll
                for (int p = 0; p < 8; p++)
                    acc[i][p] += a[p] * b[p + i];
        }

        bufc = (bufc == 2) ? 0 : bufc + 1;
    }

    // ------- store: 18 x STG.128 -------
    float* ob = out + (((size_t)n * 81 + j) * H_ + (h0 + h)) * W_ + w0 + 8 * tx;
    #pragma unroll
    for (int i = 0; i < 9; i++) {
        *(float4*)(ob + (size_t)(9 * i) * plane) =
            make_float4(acc[i][0], acc[i][1], acc[i][2], acc[i][3]);
        *(float4*)(ob + (size_t)(9 * i) * plane + 4) =
            make_float4(acc[i][4], acc[i][5], acc[i][6], acc[i][7]);
    }
}

extern "C" void kernel_launch(void* const* d_in, const int* in_sizes, int n_in,
                              void* d_out, int out_size)
{
    const float* imgA = (const float*)d_in[0];
    const float* imgB = (const float*)d_in[1];
    float* out = (float*)d_out;

    dim3 grid(W_ / TW, H_ / TH, N_);
    corr_kernel<<<grid, NT>>>(imgA, imgB, out);
}